// round 13
// baseline (speedup 1.0000x reference)
#include <cuda_runtime.h>

#define NEG_INF -1.0e9f

// Problem sizes (fixed by the reference)
#define B 8
#define N 512
#define D 256
#define DH 64

#define BM 32            // rows per attention block
#define BN 16            // K/V chunk rows
#define NC (N / BN)      // 32 chunks
#define ATTN_BLOCKS (B * (N / BM))               // 128
#define GRID_BLOCKS 888
#define E4_COUNT ((size_t)B * N * N * 32 / 4)    // 16,777,216 float4

// copy tickets (monotonic counter; advances by exactly PERIOD per execution)
#define CHUNK4 4096                               // float4 per ticket (64 KB)
#define NTICKETS 4096                             // E4_COUNT / CHUNK4
#define PERIOD ((unsigned long long)(NTICKETS + GRID_BLOCKS))   // 4984

// smem strides (floats)
#define QSTR 68
#define KSTR 68
#define PSTR 20
// dyn smem floats: Qs[32*68] + K[2][16*68] + V[2][16*68] + Ps[32*20] = 7168 (28 KB)
// qkv phase reuses [Kb0..] region (4992 floats) as a 16x256 x-half scratch (4096).
#define SMEM_FLOATS (BM * QSTR + 2 * BN * KSTR + 2 * BN * KSTR + BM * PSTR)

// Scratch (allocation-free: __device__ globals, zero-initialized once)
__device__ float d_K[B * N * DH];
__device__ float d_V[B * N * DH];
__device__ unsigned long long g_ticket;   // monotonic copy ticket
__device__ unsigned g_done[B];            // monotonic per-batch qkv done count

__device__ __forceinline__ void cp16(float* s, const float* g) {
    unsigned sa = (unsigned)__cvta_generic_to_shared(s);
    asm volatile("cp.async.cg.shared.global [%0], [%1], 16;" :: "r"(sa), "l"(g));
}
__device__ __forceinline__ void cp_commit() {
    asm volatile("cp.async.commit_group;");
}
template <int NWAIT>
__device__ __forceinline__ void cp_wait() {
    asm volatile("cp.async.wait_group %0;" :: "n"(NWAIT));
}

// ---------------------------------------------------------------------------
// Single mega-kernel, zero prefix.
//  bid <  128: qkv for own 32 rows (Q -> smem, K/V -> global) -> per-batch
//              barrier -> flash attention (R6) -> join ticket copy.
//  bid >= 128: ticket copy of e from cycle 0.
// ---------------------------------------------------------------------------
__global__ __launch_bounds__(256) void mega_kernel(
    const float* __restrict__ x, const int* __restrict__ mask,
    const float* __restrict__ Wq, const float* __restrict__ bq,
    const float* __restrict__ Wk, const float* __restrict__ bk,
    const float* __restrict__ Wv, const float* __restrict__ bv,
    float* __restrict__ out,
    const float4* __restrict__ e4, float4* __restrict__ o4) {
    extern __shared__ float sm[];
    __shared__ float jms[N];
    __shared__ unsigned long long s_tk;
    int t = threadIdx.x;

    if (blockIdx.x < ATTN_BLOCKS) {
        float* Qs = sm;                      // 32*68 (persists through attn)
        float* S = sm + BM * QSTR;           // 16*256 x-half scratch (reused later)

        int b = blockIdx.x >> 4;             // 16 i-tiles per batch
        int i0 = (blockIdx.x & 15) * BM;

        jms[t] = (float)mask[b * N + t];
        jms[t + 256] = (float)mask[b * N + t + 256];

        // ---------------- QKV: two passes of 16 rows ----------------
        int tensor = t >> 6;                 // 0=Q 1=K 2=V (3 = idle)
        int u = t & 63;
        int c4 = (u & 15) << 2;              // output cols c4..c4+3
        int rg = u >> 4;                     // local rows rg*4..rg*4+3
        const float* W = (tensor == 0) ? Wq : (tensor == 1) ? Wk : Wv;
        const float* Bb = (tensor == 0) ? bq : (tensor == 1) ? bk : bv;

#pragma unroll
        for (int p = 0; p < 2; p++) {
            // stage x rows [i0+16p, i0+16p+16) into S
            const float* xg = x + ((size_t)(b * N + i0 + p * 16)) * D;
#pragma unroll
            for (int it = 0; it < 4; it++) {
                int idx = t + 256 * it;      // float4 index, 1024 total
                int lr = idx >> 6, cc = (idx & 63) << 2;
                *(float4*)(S + lr * D + cc) = *(const float4*)(xg + lr * D + cc);
            }
            __syncthreads();

            if (t < 192) {
                float acc[4][4];
#pragma unroll
                for (int r = 0; r < 4; r++)
#pragma unroll
                    for (int c = 0; c < 4; c++) acc[r][c] = 0.f;
                const float* xr = S + (rg * 4) * D;
#pragma unroll 4
                for (int k = 0; k < D; k++) {
                    float4 w4 = *(const float4*)(W + k * DH + c4);
#pragma unroll
                    for (int r = 0; r < 4; r++) {
                        float xv = xr[r * D + k];
                        acc[r][0] = fmaf(xv, w4.x, acc[r][0]);
                        acc[r][1] = fmaf(xv, w4.y, acc[r][1]);
                        acc[r][2] = fmaf(xv, w4.z, acc[r][2]);
                        acc[r][3] = fmaf(xv, w4.w, acc[r][3]);
                    }
                }
                float4 bb = *(const float4*)(Bb + c4);
#pragma unroll
                for (int r = 0; r < 4; r++) {
                    int row = p * 16 + rg * 4 + r;      // 0..31 within tile
                    float m = jms[i0 + row];
                    float4 v;
                    v.x = (acc[r][0] + bb.x) * m;
                    v.y = (acc[r][1] + bb.y) * m;
                    v.z = (acc[r][2] + bb.z) * m;
                    v.w = (acc[r][3] + bb.w) * m;
                    if (tensor == 0) {
                        *(float4*)(Qs + row * QSTR + c4) = v;    // Q stays local
                    } else {
                        float* O = (tensor == 1) ? d_K : d_V;
                        *(float4*)(O + ((size_t)(b * N + i0 + row)) * DH + c4) = v;
                    }
                }
            }
            __syncthreads();   // S consumed before next pass overwrites it
        }

        // ---------------- per-batch barrier (monotonic) ----------------
        __threadfence();       // publish our K/V before signaling
        __syncthreads();
        if (t == 0) {
            unsigned old = atomicAdd(&g_done[b], 1u);
            unsigned target = (old & ~15u) + 16u;     // end of this exec's window
            while ((int)(atomicAdd(&g_done[b], 0u) - target) < 0) __nanosleep(64);
        }
        __syncthreads();
        __threadfence();

        // ---------------- flash attention (R6 layout) ----------------
        float* Kb0 = sm + BM * QSTR;         // 2 x 16*68 (aliases S, now dead)
        float* Vb0 = Kb0 + 2 * BN * KSTR;    // 2 x 16*68
        float* Ps = Vb0 + 2 * BN * KSTR;     // 32*20

        int tx = t & 15, ty = t >> 4;
        int i_0 = 2 * ty, i_1 = 2 * ty + 1;

        const float* Kg = d_K + b * N * DH;
        const float* Vg = d_V + b * N * DH;

        // preload chunk 0 (K and V): 16 rows x 64 floats = 256 float4 each
        {
            int row = t >> 4, cc = (t & 15) << 2;
            cp16(Kb0 + row * KSTR + cc, Kg + row * DH + cc);
            cp16(Vb0 + row * KSTR + cc, Vg + row * DH + cc);
            cp_commit();
        }

        float mi0 = jms[i0 + i_0], mi1 = jms[i0 + i_1];
        float m0 = NEG_INF, m1 = NEG_INF;
        float l0 = 0.f, l1 = 0.f;
        float o0[4] = {0.f, 0.f, 0.f, 0.f};
        float o1[4] = {0.f, 0.f, 0.f, 0.f};

        for (int jc = 0; jc < NC; jc++) {
            int buf = jc & 1;
            if (jc + 1 < NC) {
                int nb = buf ^ 1;
                const float* Kn = Kg + (jc + 1) * BN * DH;
                const float* Vn = Vg + (jc + 1) * BN * DH;
                int row = t >> 4, cc = (t & 15) << 2;
                cp16(Kb0 + nb * BN * KSTR + row * KSTR + cc, Kn + row * DH + cc);
                cp16(Vb0 + nb * BN * KSTR + row * KSTR + cc, Vn + row * DH + cc);
                cp_commit();
                cp_wait<1>();
            } else {
                cp_wait<0>();
            }
            __syncthreads();

            const float* Kc = Kb0 + buf * BN * KSTR;
            const float* Vc = Vb0 + buf * BN * KSTR;
            int j0 = jc * BN;

            // ---- scores: rows i_0,i_1; col j = tx ----
            float a0 = 0.f, a1 = 0.f;
#pragma unroll
            for (int k4 = 0; k4 < 16; k4++) {
                float4 q0 = *(const float4*)(Qs + i_0 * QSTR + 4 * k4);
                float4 q1 = *(const float4*)(Qs + i_1 * QSTR + 4 * k4);
                float4 kk = *(const float4*)(Kc + tx * KSTR + 4 * k4);
                a0 = fmaf(q0.x, kk.x, a0); a0 = fmaf(q0.y, kk.y, a0);
                a0 = fmaf(q0.z, kk.z, a0); a0 = fmaf(q0.w, kk.w, a0);
                a1 = fmaf(q1.x, kk.x, a1); a1 = fmaf(q1.y, kk.y, a1);
                a1 = fmaf(q1.z, kk.z, a1); a1 = fmaf(q1.w, kk.w, a1);
            }
            float mj = jms[j0 + tx];
            float s0 = (mi0 * mj != 0.f) ? a0 * 0.125f : NEG_INF;
            float s1 = (mi1 * mj != 0.f) ? a1 * 0.125f : NEG_INF;

            float mc0 = s0, mc1 = s1;
#pragma unroll
            for (int d = 8; d; d >>= 1) {
                mc0 = fmaxf(mc0, __shfl_xor_sync(0xffffffffu, mc0, d));
                mc1 = fmaxf(mc1, __shfl_xor_sync(0xffffffffu, mc1, d));
            }
            float mn0 = fmaxf(m0, mc0), mn1 = fmaxf(m1, mc1);
            float al0 = __expf(m0 - mn0), al1 = __expf(m1 - mn1);
            m0 = mn0; m1 = mn1;
            float p0 = __expf(s0 - mn0);
            float p1 = __expf(s1 - mn1);
            Ps[i_0 * PSTR + tx] = p0;
            Ps[i_1 * PSTR + tx] = p1;
            float ls0 = p0, ls1 = p1;
#pragma unroll
            for (int d = 8; d; d >>= 1) {
                ls0 += __shfl_xor_sync(0xffffffffu, ls0, d);
                ls1 += __shfl_xor_sync(0xffffffffu, ls1, d);
            }
            l0 = l0 * al0 + ls0;
            l1 = l1 * al1 + ls1;
#pragma unroll
            for (int uu = 0; uu < 4; uu++) { o0[uu] *= al0; o1[uu] *= al1; }

            __syncwarp();   // P rows 4w..4w+3 produced & consumed within warp w

            // ---- o += P @ V: output cols 4tx+u ----
#pragma unroll
            for (int jj4 = 0; jj4 < 4; jj4++) {
                float4 pa = *(const float4*)(Ps + i_0 * PSTR + 4 * jj4);
                float4 pb = *(const float4*)(Ps + i_1 * PSTR + 4 * jj4);
                const float* Vrow = Vc + (4 * jj4) * KSTR + 4 * tx;
                float4 v0 = *(const float4*)(Vrow);
                float4 v1 = *(const float4*)(Vrow + KSTR);
                float4 v2 = *(const float4*)(Vrow + 2 * KSTR);
                float4 v3 = *(const float4*)(Vrow + 3 * KSTR);
                o0[0] = fmaf(pa.x, v0.x, o0[0]); o0[1] = fmaf(pa.x, v0.y, o0[1]);
                o0[2] = fmaf(pa.x, v0.z, o0[2]); o0[3] = fmaf(pa.x, v0.w, o0[3]);
                o0[0] = fmaf(pa.y, v1.x, o0[0]); o0[1] = fmaf(pa.y, v1.y, o0[1]);
                o0[2] = fmaf(pa.y, v1.z, o0[2]); o0[3] = fmaf(pa.y, v1.w, o0[3]);
                o0[0] = fmaf(pa.z, v2.x, o0[0]); o0[1] = fmaf(pa.z, v2.y, o0[1]);
                o0[2] = fmaf(pa.z, v2.z, o0[2]); o0[3] = fmaf(pa.z, v2.w, o0[3]);
                o0[0] = fmaf(pa.w, v3.x, o0[0]); o0[1] = fmaf(pa.w, v3.y, o0[1]);
                o0[2] = fmaf(pa.w, v3.z, o0[2]); o0[3] = fmaf(pa.w, v3.w, o0[3]);
                o1[0] = fmaf(pb.x, v0.x, o1[0]); o1[1] = fmaf(pb.x, v0.y, o1[1]);
                o1[2] = fmaf(pb.x, v0.z, o1[2]); o1[3] = fmaf(pb.x, v0.w, o1[3]);
                o1[0] = fmaf(pb.y, v1.x, o1[0]); o1[1] = fmaf(pb.y, v1.y, o1[1]);
                o1[2] = fmaf(pb.y, v1.z, o1[2]); o1[3] = fmaf(pb.y, v1.w, o1[3]);
                o1[0] = fmaf(pb.z, v2.x, o1[0]); o1[1] = fmaf(pb.z, v2.y, o1[1]);
                o1[2] = fmaf(pb.z, v2.z, o1[2]); o1[3] = fmaf(pb.z, v2.w, o1[3]);
                o1[0] = fmaf(pb.w, v3.x, o1[0]); o1[1] = fmaf(pb.w, v3.y, o1[1]);
                o1[2] = fmaf(pb.w, v3.z, o1[2]); o1[3] = fmaf(pb.w, v3.w, o1[3]);
            }
            __syncthreads();   // buf fully consumed before overwrite
        }

        float f0 = mi0 / l0;   // l >= 1 always
        float f1 = mi1 / l1;
        float4 r0, r1;
        r0.x = o0[0] * f0; r0.y = o0[1] * f0; r0.z = o0[2] * f0; r0.w = o0[3] * f0;
        r1.x = o1[0] * f1; r1.y = o1[1] * f1; r1.z = o1[2] * f1; r1.w = o1[3] * f1;
        *(float4*)(out + (b * N + i0 + i_0) * DH + 4 * tx) = r0;
        *(float4*)(out + (b * N + i0 + i_1) * DH + 4 * tx) = r1;
        __syncthreads();
    }

    // ---- ticket copy of e (all blocks; attn blocks join after attn) ----
    // Monotonic ticket: each execution consumes exactly PERIOD draws
    // (NTICKETS valid + one terminating draw per block).
    for (;;) {
        if (t == 0) s_tk = atomicAdd(&g_ticket, 1ULL);
        __syncthreads();
        unsigned long long tk = s_tk;
        __syncthreads();
        unsigned rel = (unsigned)(tk % PERIOD);
        if (rel >= NTICKETS) break;
        size_t base = (size_t)rel * CHUNK4 + t;
        float4 r[8];
#pragma unroll
        for (int k = 0; k < 8; k++) r[k] = e4[base + 256 * k];
#pragma unroll
        for (int k = 0; k < 8; k++) o4[base + 256 * k] = r[k];
        base += 2048;
#pragma unroll
        for (int k = 0; k < 8; k++) r[k] = e4[base + 256 * k];
#pragma unroll
        for (int k = 0; k < 8; k++) o4[base + 256 * k] = r[k];
    }
}

extern "C" void kernel_launch(void* const* d_in, const int* in_sizes, int n_in,
                              void* d_out, int out_size) {
    const float* x  = (const float*)d_in[0];
    const float* e  = (const float*)d_in[1];
    const int* mask = (const int*)d_in[2];
    const float* Wq = (const float*)d_in[3];
    const float* bq = (const float*)d_in[4];
    const float* Wk = (const float*)d_in[5];
    const float* bk = (const float*)d_in[6];
    const float* Wv = (const float*)d_in[7];
    const float* bv = (const float*)d_in[8];
    float* out = (float*)d_out;

    (void)in_sizes; (void)n_in; (void)out_size;

    const size_t OUT_ELEMS = (size_t)B * N * DH;   // 262144

    static bool attr_set = false;
    if (!attr_set) {
        cudaFuncSetAttribute(mega_kernel, cudaFuncAttributeMaxDynamicSharedMemorySize,
                             SMEM_FLOATS * (int)sizeof(float));
        attr_set = true;
    }

    mega_kernel<<<GRID_BLOCKS, 256, SMEM_FLOATS * sizeof(float)>>>(
        x, mask, Wq, bq, Wk, bk, Wv, bv, out,
        (const float4*)e, (float4*)(out + OUT_ELEMS));
}

// round 16
// speedup vs baseline: 1.7827x; 1.7827x over previous
#include <cuda_runtime.h>

#define NEG_INF -1.0e9f

// Problem sizes (fixed by the reference)
#define B 8
#define N 512
#define D 256
#define DH 64

#define BM 32            // rows per attention block
#define BN 16            // K/V chunk rows
#define NC (N / BN)      // 32 chunks
#define ATTN_BLOCKS (B * (N / BM))               // 128
#define GRID_BLOCKS 888
#define E4_COUNT ((size_t)B * N * N * 32 / 4)    // 16,777,216 float4

// copy tickets
#define CHUNK4 4096                               // float4 per ticket (64 KB)
#define NTICKETS (int)(E4_COUNT / CHUNK4)         // 4096

// smem strides (floats)
#define QSTR 68
#define KSTR 68
#define PSTR 20
// dyn smem floats: Qs[32*68] + K[2][16*68] + V[2][16*68] + Ps[32*20] = 7168 (28 KB)
#define SMEM_FLOATS (BM * QSTR + 2 * BN * KSTR + 2 * BN * KSTR + BM * PSTR)

// Scratch (allocation-free: __device__ globals)
__device__ float d_Q[B * N * DH];
__device__ float d_K[B * N * DH];
__device__ float d_V[B * N * DH];
__device__ int g_ticket;

__device__ __forceinline__ void cp16(float* s, const float* g) {
    unsigned sa = (unsigned)__cvta_generic_to_shared(s);
    asm volatile("cp.async.cg.shared.global [%0], [%1], 16;" :: "r"(sa), "l"(g));
}
__device__ __forceinline__ void cp_commit() {
    asm volatile("cp.async.commit_group;");
}
template <int NWAIT>
__device__ __forceinline__ void cp_wait() {
    asm volatile("cp.async.wait_group %0;" :: "n"(NWAIT));
}

// ---------------------------------------------------------------------------
// QKV projection, tensor-specialized: 384 blocks. Block = (tensor = bid%3,
// 32-row tile = bid/3). Per-block W working set = ONE 64 KB matrix ->
// L1-resident. 256 threads, acc[2][4] per thread: per k = 1 coalesced W
// float4 load + 2 smem broadcasts + 8 FMAs. Block 0 resets the copy ticket.
// ---------------------------------------------------------------------------
__global__ __launch_bounds__(256) void qkv_kernel(
    const float* __restrict__ x, const int* __restrict__ mask,
    const float* __restrict__ Wq, const float* __restrict__ bq,
    const float* __restrict__ Wk, const float* __restrict__ bk,
    const float* __restrict__ Wv, const float* __restrict__ bv) {
    __shared__ float xs[BM * D];   // 32 KB
    int t = threadIdx.x;
    if (blockIdx.x == 0 && t == 0) g_ticket = 0;   // reset for fused kernel

    int T = blockIdx.x % 3;                  // 0=Q 1=K 2=V
    int tile = blockIdx.x / 3;               // 0..127
    size_t r0 = (size_t)tile * BM;

    const float* xg = x + r0 * D;
#pragma unroll
    for (int it = 0; it < 8; it++) {
        int idx = t + 256 * it;              // float4 index, 2048 total
        int r = idx >> 6, c4 = (idx & 63) << 2;
        *(float4*)(xs + r * D + c4) = *(const float4*)(xg + r * D + c4);
    }
    __syncthreads();

    const float* W = (T == 0) ? Wq : (T == 1) ? Wk : Wv;
    const float* Bb = (T == 0) ? bq : (T == 1) ? bk : bv;
    float* O = (T == 0) ? d_Q : (T == 1) ? d_K : d_V;

    int c4 = (t & 15) << 2;                  // output cols c4..c4+3
    int rg = t >> 4;                         // 0..15 -> rows 2rg, 2rg+1
    const float* x0 = xs + (2 * rg) * D;
    const float* x1 = x0 + D;

    float a0[4] = {0.f, 0.f, 0.f, 0.f};
    float a1[4] = {0.f, 0.f, 0.f, 0.f};
#pragma unroll 8
    for (int k = 0; k < D; k++) {
        float4 w4 = *(const float4*)(W + k * DH + c4);
        float xv0 = x0[k], xv1 = x1[k];
        a0[0] = fmaf(xv0, w4.x, a0[0]); a0[1] = fmaf(xv0, w4.y, a0[1]);
        a0[2] = fmaf(xv0, w4.z, a0[2]); a0[3] = fmaf(xv0, w4.w, a0[3]);
        a1[0] = fmaf(xv1, w4.x, a1[0]); a1[1] = fmaf(xv1, w4.y, a1[1]);
        a1[2] = fmaf(xv1, w4.z, a1[2]); a1[3] = fmaf(xv1, w4.w, a1[3]);
    }
    float4 bb = *(const float4*)(Bb + c4);
    size_t row0 = r0 + 2 * rg;
    float m0 = (float)mask[row0];
    float m1 = (float)mask[row0 + 1];
    float4 v0, v1;
    v0.x = (a0[0] + bb.x) * m0; v0.y = (a0[1] + bb.y) * m0;
    v0.z = (a0[2] + bb.z) * m0; v0.w = (a0[3] + bb.w) * m0;
    v1.x = (a1[0] + bb.x) * m1; v1.y = (a1[1] + bb.y) * m1;
    v1.z = (a1[2] + bb.z) * m1; v1.w = (a1[3] + bb.w) * m1;
    *(float4*)(O + row0 * DH + c4) = v0;
    *(float4*)(O + (row0 + 1) * DH + c4) = v1;
}

// ---------------------------------------------------------------------------
// Fused kernel (R6/R10, measured 91.3us): blocks < ATTN_BLOCKS do flash
// attention on a 32-row i-tile then fall through to ticket copy; others copy.
// ---------------------------------------------------------------------------
__global__ __launch_bounds__(256) void fused_kernel(const int* __restrict__ mask,
                                                    float* __restrict__ out,
                                                    const float4* __restrict__ e4,
                                                    float4* __restrict__ o4) {
    extern __shared__ float sm[];
    __shared__ float jms[N];
    __shared__ int s_tk;
    int t = threadIdx.x;

    if (blockIdx.x < ATTN_BLOCKS) {
        float* Qs = sm;                      // 32*68
        float* Kb0 = Qs + BM * QSTR;         // 2 x 16*68
        float* Vb0 = Kb0 + 2 * BN * KSTR;    // 2 x 16*68
        float* Ps = Vb0 + 2 * BN * KSTR;     // 32*20

        int b = blockIdx.x >> 4;             // 16 i-tiles per batch
        int i0 = (blockIdx.x & 15) * BM;
        int tx = t & 15, ty = t >> 4;
        int i_0 = 2 * ty, i_1 = 2 * ty + 1;

        const float* Qg = d_Q + (b * N + i0) * DH;
        const float* Kg = d_K + b * N * DH;
        const float* Vg = d_V + b * N * DH;

        for (int l = t; l < BM * DH; l += 256) {
            int r = l >> 6, c = l & 63;
            Qs[r * QSTR + c] = Qg[r * DH + c];
        }
        jms[t] = (float)mask[b * N + t];
        jms[t + 256] = (float)mask[b * N + t + 256];

        // preload chunk 0 (K and V): 16 rows x 64 floats = 256 float4 each
        {
            int row = t >> 4, c4 = (t & 15) << 2;
            cp16(Kb0 + row * KSTR + c4, Kg + row * DH + c4);
            cp16(Vb0 + row * KSTR + c4, Vg + row * DH + c4);
            cp_commit();
        }
        __syncthreads();

        float mi0 = jms[i0 + i_0], mi1 = jms[i0 + i_1];
        float m0 = NEG_INF, m1 = NEG_INF;
        float l0 = 0.f, l1 = 0.f;
        float o0[4] = {0.f, 0.f, 0.f, 0.f};
        float o1[4] = {0.f, 0.f, 0.f, 0.f};

        for (int jc = 0; jc < NC; jc++) {
            int buf = jc & 1;
            if (jc + 1 < NC) {
                int nb = buf ^ 1;
                const float* Kn = Kg + (jc + 1) * BN * DH;
                const float* Vn = Vg + (jc + 1) * BN * DH;
                int row = t >> 4, c4 = (t & 15) << 2;
                cp16(Kb0 + nb * BN * KSTR + row * KSTR + c4, Kn + row * DH + c4);
                cp16(Vb0 + nb * BN * KSTR + row * KSTR + c4, Vn + row * DH + c4);
                cp_commit();
                cp_wait<1>();
            } else {
                cp_wait<0>();
            }
            __syncthreads();

            const float* Kc = Kb0 + buf * BN * KSTR;
            const float* Vc = Vb0 + buf * BN * KSTR;
            int j0 = jc * BN;

            // ---- scores: rows i_0,i_1; col j = tx ----
            float a0 = 0.f, a1 = 0.f;
#pragma unroll
            for (int k4 = 0; k4 < 16; k4++) {
                float4 q0 = *(const float4*)(Qs + i_0 * QSTR + 4 * k4);
                float4 q1 = *(const float4*)(Qs + i_1 * QSTR + 4 * k4);
                float4 kk = *(const float4*)(Kc + tx * KSTR + 4 * k4);
                a0 = fmaf(q0.x, kk.x, a0); a0 = fmaf(q0.y, kk.y, a0);
                a0 = fmaf(q0.z, kk.z, a0); a0 = fmaf(q0.w, kk.w, a0);
                a1 = fmaf(q1.x, kk.x, a1); a1 = fmaf(q1.y, kk.y, a1);
                a1 = fmaf(q1.z, kk.z, a1); a1 = fmaf(q1.w, kk.w, a1);
            }
            float mj = jms[j0 + tx];
            float s0 = (mi0 * mj != 0.f) ? a0 * 0.125f : NEG_INF;
            float s1 = (mi1 * mj != 0.f) ? a1 * 0.125f : NEG_INF;

            float mc0 = s0, mc1 = s1;
#pragma unroll
            for (int d = 8; d; d >>= 1) {
                mc0 = fmaxf(mc0, __shfl_xor_sync(0xffffffffu, mc0, d));
                mc1 = fmaxf(mc1, __shfl_xor_sync(0xffffffffu, mc1, d));
            }
            float mn0 = fmaxf(m0, mc0), mn1 = fmaxf(m1, mc1);
            float al0 = __expf(m0 - mn0), al1 = __expf(m1 - mn1);
            m0 = mn0; m1 = mn1;
            float p0 = __expf(s0 - mn0);
            float p1 = __expf(s1 - mn1);
            Ps[i_0 * PSTR + tx] = p0;
            Ps[i_1 * PSTR + tx] = p1;
            float ls0 = p0, ls1 = p1;
#pragma unroll
            for (int d = 8; d; d >>= 1) {
                ls0 += __shfl_xor_sync(0xffffffffu, ls0, d);
                ls1 += __shfl_xor_sync(0xffffffffu, ls1, d);
            }
            l0 = l0 * al0 + ls0;
            l1 = l1 * al1 + ls1;
#pragma unroll
            for (int u = 0; u < 4; u++) { o0[u] *= al0; o1[u] *= al1; }

            __syncwarp();   // P rows 4w..4w+3 produced & consumed within warp w

            // ---- o += P @ V: output cols 4tx+u ----
#pragma unroll
            for (int jj4 = 0; jj4 < 4; jj4++) {
                float4 pa = *(const float4*)(Ps + i_0 * PSTR + 4 * jj4);
                float4 pb = *(const float4*)(Ps + i_1 * PSTR + 4 * jj4);
                const float* Vrow = Vc + (4 * jj4) * KSTR + 4 * tx;
                float4 v0 = *(const float4*)(Vrow);
                float4 v1 = *(const float4*)(Vrow + KSTR);
                float4 v2 = *(const float4*)(Vrow + 2 * KSTR);
                float4 v3 = *(const float4*)(Vrow + 3 * KSTR);
                o0[0] = fmaf(pa.x, v0.x, o0[0]); o0[1] = fmaf(pa.x, v0.y, o0[1]);
                o0[2] = fmaf(pa.x, v0.z, o0[2]); o0[3] = fmaf(pa.x, v0.w, o0[3]);
                o0[0] = fmaf(pa.y, v1.x, o0[0]); o0[1] = fmaf(pa.y, v1.y, o0[1]);
                o0[2] = fmaf(pa.y, v1.z, o0[2]); o0[3] = fmaf(pa.y, v1.w, o0[3]);
                o0[0] = fmaf(pa.z, v2.x, o0[0]); o0[1] = fmaf(pa.z, v2.y, o0[1]);
                o0[2] = fmaf(pa.z, v2.z, o0[2]); o0[3] = fmaf(pa.z, v2.w, o0[3]);
                o0[0] = fmaf(pa.w, v3.x, o0[0]); o0[1] = fmaf(pa.w, v3.y, o0[1]);
                o0[2] = fmaf(pa.w, v3.z, o0[2]); o0[3] = fmaf(pa.w, v3.w, o0[3]);
                o1[0] = fmaf(pb.x, v0.x, o1[0]); o1[1] = fmaf(pb.x, v0.y, o1[1]);
                o1[2] = fmaf(pb.x, v0.z, o1[2]); o1[3] = fmaf(pb.x, v0.w, o1[3]);
                o1[0] = fmaf(pb.y, v1.x, o1[0]); o1[1] = fmaf(pb.y, v1.y, o1[1]);
                o1[2] = fmaf(pb.y, v1.z, o1[2]); o1[3] = fmaf(pb.y, v1.w, o1[3]);
                o1[0] = fmaf(pb.z, v2.x, o1[0]); o1[1] = fmaf(pb.z, v2.y, o1[1]);
                o1[2] = fmaf(pb.z, v2.z, o1[2]); o1[3] = fmaf(pb.z, v2.w, o1[3]);
                o1[0] = fmaf(pb.w, v3.x, o1[0]); o1[1] = fmaf(pb.w, v3.y, o1[1]);
                o1[2] = fmaf(pb.w, v3.z, o1[2]); o1[3] = fmaf(pb.w, v3.w, o1[3]);
            }
            __syncthreads();   // buf fully consumed before overwrite
        }

        float f0 = mi0 / l0;   // l >= 1 always
        float f1 = mi1 / l1;
        float4 r0, r1;
        r0.x = o0[0] * f0; r0.y = o0[1] * f0; r0.z = o0[2] * f0; r0.w = o0[3] * f0;
        r1.x = o1[0] * f1; r1.y = o1[1] * f1; r1.z = o1[2] * f1; r1.w = o1[3] * f1;
        *(float4*)(out + (b * N + i0 + i_0) * DH + 4 * tx) = r0;
        *(float4*)(out + (b * N + i0 + i_1) * DH + 4 * tx) = r1;
        __syncthreads();
    }

    // ---- ticket-based copy of e (all blocks; attn blocks join after attn) ----
    for (;;) {
        if (t == 0) s_tk = atomicAdd(&g_ticket, 1);
        __syncthreads();
        int tk = s_tk;
        __syncthreads();
        if (tk >= NTICKETS) break;
        size_t base = (size_t)tk * CHUNK4 + t;
        float4 r[8];
#pragma unroll
        for (int k = 0; k < 8; k++) r[k] = e4[base + 256 * k];
#pragma unroll
        for (int k = 0; k < 8; k++) o4[base + 256 * k] = r[k];
        base += 2048;
#pragma unroll
        for (int k = 0; k < 8; k++) r[k] = e4[base + 256 * k];
#pragma unroll
        for (int k = 0; k < 8; k++) o4[base + 256 * k] = r[k];
    }
}

extern "C" void kernel_launch(void* const* d_in, const int* in_sizes, int n_in,
                              void* d_out, int out_size) {
    const float* x  = (const float*)d_in[0];
    const float* e  = (const float*)d_in[1];
    const int* mask = (const int*)d_in[2];
    const float* Wq = (const float*)d_in[3];
    const float* bq = (const float*)d_in[4];
    const float* Wk = (const float*)d_in[5];
    const float* bk = (const float*)d_in[6];
    const float* Wv = (const float*)d_in[7];
    const float* bv = (const float*)d_in[8];
    float* out = (float*)d_out;

    (void)in_sizes; (void)n_in; (void)out_size;

    const size_t OUT_ELEMS = (size_t)B * N * DH;   // 262144

    static bool attr_set = false;
    if (!attr_set) {
        cudaFuncSetAttribute(fused_kernel, cudaFuncAttributeMaxDynamicSharedMemorySize,
                             SMEM_FLOATS * (int)sizeof(float));
        attr_set = true;
    }

    qkv_kernel<<<3 * (B * N / BM), 256>>>(x, mask, Wq, bq, Wk, bk, Wv, bv);
    fused_kernel<<<GRID_BLOCKS, 256, SMEM_FLOATS * sizeof(float)>>>(
        mask, out, (const float4*)e, (float4*)(out + OUT_ELEMS));
}